// round 5
// baseline (speedup 1.0000x reference)
#include <cuda_runtime.h>
#include <cuda_bf16.h>

// Problem constants
#define BATCH   64
#define HW      56
#define CDIM    256
#define WS      7
#define SHIFT_  3
#define HEADS   8
#define HD      32
#define NWIN    64                      // 8*8 windows per image
#define NTOK    49                      // 7*7 tokens per window
#define BW_TOT  (BATCH*NWIN)            // 4096 window instances
#define M_TOT   (BW_TOT*NTOK)           // 200704 token rows

// ---------------------------------------------------------------------------
// Scratch (device globals: no runtime allocation allowed)
// ---------------------------------------------------------------------------
__device__ float g_q [(size_t)BW_TOT*HEADS*NTOK*HD];   // [bw, head, n, d]
__device__ float g_k [(size_t)BW_TOT*HEADS*NTOK*HD];
__device__ float g_v [(size_t)BW_TOT*HEADS*NTOK*HD];
__device__ float g_ao[(size_t)M_TOT*CDIM];             // attention output [m, C]

// ---------------------------------------------------------------------------
// Kernel 1: QKV GEMM  out[m, 0:768] = gather(x)[m, :] @ Wqkv^T + b
//   gather: window-partition + cyclic roll folded into A-row offsets
//   epilogue: scatter into g_q/g_k/g_v, q pre-scaled by hd^-0.5
// Tiling: 128x64 tile, BK=16, 256 threads, 8x4 micro-tile
// ---------------------------------------------------------------------------
__global__ __launch_bounds__(256) void qkv_gemm(
    const float* __restrict__ x,
    const float* __restrict__ W,
    const float* __restrict__ bias)
{
    __shared__ float As[128][17];
    __shared__ float Bs[64][17];
    __shared__ int   rowoff[128];

    const int tid = threadIdx.x;
    const int m0  = blockIdx.y * 128;
    const int n0  = blockIdx.x * 64;

    if (tid < 128) {
        int m    = m0 + tid;
        int bw   = m / 49;
        int n    = m - bw * 49;
        int b    = bw >> 6;
        int widx = bw & 63;
        int wh   = widx >> 3, ww = widx & 7;
        int r    = n / 7,     c  = n - (n / 7) * 7;
        int h = wh * 7 + r + SHIFT_; if (h >= HW) h -= HW;
        int w = ww * 7 + c + SHIFT_; if (w >= HW) w -= HW;
        rowoff[tid] = ((b * HW + h) * HW + w) << 8;   // *256 floats
    }
    __syncthreads();

    const int cx = tid & 15;        // output col group
    const int cy = tid >> 4;        // output row group
    float acc[8][4];
    #pragma unroll
    for (int i = 0; i < 8; i++)
        #pragma unroll
        for (int j = 0; j < 4; j++) acc[i][j] = 0.f;

    const int lrow = tid >> 2;          // 0..63
    const int lcol = (tid & 3) << 2;    // 0,4,8,12

    for (int kt = 0; kt < CDIM; kt += 16) {
        #pragma unroll
        for (int l = 0; l < 2; l++) {
            int row = lrow + l * 64;
            float4 v4 = *reinterpret_cast<const float4*>(x + rowoff[row] + kt + lcol);
            As[row][lcol+0] = v4.x; As[row][lcol+1] = v4.y;
            As[row][lcol+2] = v4.z; As[row][lcol+3] = v4.w;
        }
        {
            float4 v4 = *reinterpret_cast<const float4*>(
                W + (size_t)(n0 + lrow) * CDIM + kt + lcol);
            Bs[lrow][lcol+0] = v4.x; Bs[lrow][lcol+1] = v4.y;
            Bs[lrow][lcol+2] = v4.z; Bs[lrow][lcol+3] = v4.w;
        }
        __syncthreads();
        #pragma unroll
        for (int k = 0; k < 16; k++) {
            float a[8], b[4];
            #pragma unroll
            for (int i = 0; i < 8; i++) a[i] = As[cy*8 + i][k];
            #pragma unroll
            for (int j = 0; j < 4; j++) b[j] = Bs[cx*4 + j][k];
            #pragma unroll
            for (int i = 0; i < 8; i++)
                #pragma unroll
                for (int j = 0; j < 4; j++)
                    acc[i][j] = fmaf(a[i], b[j], acc[i][j]);
        }
        __syncthreads();
    }

    #pragma unroll
    for (int i = 0; i < 8; i++) {
        int m  = m0 + cy*8 + i;
        int bw = m / 49;
        int n  = m - bw * 49;
        #pragma unroll
        for (int j = 0; j < 4; j++) {
            int col   = n0 + cx*4 + j;
            float val = acc[i][j] + bias[col];
            int which = col >> 8;
            int head  = (col >> 5) & 7;
            int d     = col & 31;
            size_t off = (((size_t)bw * HEADS + head) * NTOK + n) * HD + d;
            if      (which == 0) g_q[off] = val * 0.17677669529663687f; // hd^-0.5
            else if (which == 1) g_k[off] = val;
            else                 g_v[off] = val;
        }
    }
}

// ---------------------------------------------------------------------------
// Kernel 2: windowed attention, one block per (window-instance, head)
//   scores = q·k^T + rel_pos_bias + shift_mask ; softmax ; out = scores @ v
// ---------------------------------------------------------------------------
__global__ __launch_bounds__(128) void attn_kernel(const float* __restrict__ rel_table)
{
    const int bw   = blockIdx.x >> 3;
    const int head = blockIdx.x & 7;
    const int tid  = threadIdx.x;

    __shared__ float qs[49][33];
    __shared__ float ks[49][33];
    __shared__ float vs[49][33];
    __shared__ float at[49][50];
    __shared__ float tab[169];
    __shared__ unsigned char regid[49];

    const size_t base = ((size_t)bw * HEADS + head) * NTOK * HD;
    for (int i = tid; i < NTOK*HD; i += 128) {
        int row = i >> 5, d = i & 31;
        qs[row][d] = g_q[base + i];
        ks[row][d] = g_k[base + i];
        vs[row][d] = g_v[base + i];
    }
    for (int i = tid; i < 169; i += 128) tab[i] = rel_table[i * HEADS + head];
    if (tid < 49) {
        int widx = bw & 63;
        int wh = widx >> 3, ww = widx & 7;
        int r = tid / 7, c = tid - (tid / 7) * 7;
        int hs = wh * 7 + r, wsp = ww * 7 + c;
        int hr = (hs  < HW - WS) ? 0 : (hs  < HW - SHIFT_ ? 1 : 2);
        int wr = (wsp < HW - WS) ? 0 : (wsp < HW - SHIFT_ ? 1 : 2);
        regid[tid] = (unsigned char)(hr * 3 + wr);
    }
    __syncthreads();

    for (int s = tid; s < NTOK*NTOK; s += 128) {
        int n = s / 49, m = s - (s / 49) * 49;
        float acc = 0.f;
        #pragma unroll
        for (int kk = 0; kk < HD; kk++) acc = fmaf(qs[n][kk], ks[m][kk], acc);
        int r1 = n / 7, c1 = n - (n / 7) * 7;
        int r2 = m / 7, c2 = m - (m / 7) * 7;
        acc += tab[(r1 - r2 + 6) * 13 + (c1 - c2 + 6)];
        if (regid[n] != regid[m]) acc -= 100.f;
        at[n][m] = acc;
    }
    __syncthreads();

    if (tid < 49) {
        float mx = -1e30f;
        #pragma unroll 7
        for (int m = 0; m < 49; m++) mx = fmaxf(mx, at[tid][m]);
        float sum = 0.f;
        #pragma unroll 7
        for (int m = 0; m < 49; m++) {
            float e = __expf(at[tid][m] - mx);
            at[tid][m] = e;
            sum += e;
        }
        float inv = 1.f / sum;
        #pragma unroll 7
        for (int m = 0; m < 49; m++) at[tid][m] *= inv;
    }
    __syncthreads();

    for (int s = tid; s < NTOK*HD; s += 128) {
        int n = s >> 5, d = s & 31;
        float acc = 0.f;
        #pragma unroll 7
        for (int m = 0; m < 49; m++) acc = fmaf(at[n][m], vs[m][d], acc);
        g_ao[((size_t)bw * NTOK + n) * CDIM + head * HD + d] = acc;
    }
}

// ---------------------------------------------------------------------------
// Kernel 3: proj GEMM  out_token[m, 0:256] = g_ao[m, :] @ Wproj^T + b
//   epilogue scatters through window-unpartition + inverse roll into d_out
// ---------------------------------------------------------------------------
__global__ __launch_bounds__(256) void proj_gemm(
    const float* __restrict__ W,
    const float* __restrict__ bias,
    float* __restrict__ out)
{
    __shared__ float As[128][17];
    __shared__ float Bs[64][17];

    const int tid = threadIdx.x;
    const int m0  = blockIdx.y * 128;
    const int n0  = blockIdx.x * 64;
    const int cx  = tid & 15, cy = tid >> 4;

    float acc[8][4];
    #pragma unroll
    for (int i = 0; i < 8; i++)
        #pragma unroll
        for (int j = 0; j < 4; j++) acc[i][j] = 0.f;

    const int lrow = tid >> 2;
    const int lcol = (tid & 3) << 2;

    for (int kt = 0; kt < CDIM; kt += 16) {
        #pragma unroll
        for (int l = 0; l < 2; l++) {
            int row = lrow + l * 64;
            float4 v4 = *reinterpret_cast<const float4*>(
                g_ao + (size_t)(m0 + row) * CDIM + kt + lcol);
            As[row][lcol+0] = v4.x; As[row][lcol+1] = v4.y;
            As[row][lcol+2] = v4.z; As[row][lcol+3] = v4.w;
        }
        {
            float4 v4 = *reinterpret_cast<const float4*>(
                W + (size_t)(n0 + lrow) * CDIM + kt + lcol);
            Bs[lrow][lcol+0] = v4.x; Bs[lrow][lcol+1] = v4.y;
            Bs[lrow][lcol+2] = v4.z; Bs[lrow][lcol+3] = v4.w;
        }
        __syncthreads();
        #pragma unroll
        for (int k = 0; k < 16; k++) {
            float a[8], b[4];
            #pragma unroll
            for (int i = 0; i < 8; i++) a[i] = As[cy*8 + i][k];
            #pragma unroll
            for (int j = 0; j < 4; j++) b[j] = Bs[cx*4 + j][k];
            #pragma unroll
            for (int i = 0; i < 8; i++)
                #pragma unroll
                for (int j = 0; j < 4; j++)
                    acc[i][j] = fmaf(a[i], b[j], acc[i][j]);
        }
        __syncthreads();
    }

    #pragma unroll
    for (int i = 0; i < 8; i++) {
        int m    = m0 + cy*8 + i;
        int bw   = m / 49;
        int n    = m - bw * 49;
        int b    = bw >> 6;
        int widx = bw & 63;
        int wh   = widx >> 3, ww = widx & 7;
        int r    = n / 7,     c  = n - (n / 7) * 7;
        int h = wh * 7 + r + SHIFT_; if (h >= HW) h -= HW;
        int w = ww * 7 + c + SHIFT_; if (w >= HW) w -= HW;
        size_t obase = ((size_t)(b * HW + h) * HW + w) * CDIM;
        #pragma unroll
        for (int j = 0; j < 4; j++) {
            int col = n0 + cx*4 + j;
            out[obase + col] = acc[i][j] + bias[col];
        }
    }
}

// ---------------------------------------------------------------------------
// Launch
// ---------------------------------------------------------------------------
extern "C" void kernel_launch(void* const* d_in, const int* in_sizes, int n_in,
                              void* d_out, int out_size)
{
    const float* x     = (const float*)d_in[0];
    const float* qkvw  = (const float*)d_in[1];
    const float* qkvb  = (const float*)d_in[2];
    const float* projw = (const float*)d_in[3];
    const float* projb = (const float*)d_in[4];
    const float* relt  = (const float*)d_in[5];
    float* out = (float*)d_out;

    dim3 g1(3 * CDIM / 64, M_TOT / 128);   // (12, 1568)
    qkv_gemm<<<g1, 256>>>(x, qkvw, qkvb);

    attn_kernel<<<BW_TOT * HEADS, 128>>>(relt);

    dim3 g3(CDIM / 64, M_TOT / 128);       // (4, 1568)
    proj_gemm<<<g3, 256>>>(projw, projb, out);
}

// round 8
// speedup vs baseline: 1.7366x; 1.7366x over previous
#include <cuda_runtime.h>
#include <cuda_bf16.h>

// Problem constants
#define BATCH   64
#define HW      56
#define CDIM    256
#define WS      7
#define SHIFT_  3
#define HEADS   8
#define HD      32
#define NTOK    49
#define BW_TOT  (BATCH*64)              // 4096 window instances
#define M_TOT   (BW_TOT*NTOK)           // 200704 token rows

// ---------------------------------------------------------------------------
// Scratch (device globals: no runtime allocation allowed)
// ---------------------------------------------------------------------------
__device__ float g_q [(size_t)BW_TOT*HEADS*NTOK*HD];   // [bw, head, n, d]
__device__ float g_k [(size_t)BW_TOT*HEADS*NTOK*HD];
__device__ float g_v [(size_t)BW_TOT*HEADS*NTOK*HD];
__device__ float g_ao[(size_t)M_TOT*CDIM];             // attention output [m, C]

// ---------------------------------------------------------------------------
// tf32 helpers
// ---------------------------------------------------------------------------
__device__ __forceinline__ unsigned f2tf32(float f) {
    unsigned u;
    asm("cvt.rna.tf32.f32 %0, %1;" : "=r"(u) : "f"(f));
    return u;
}

__device__ __forceinline__ void mma_tf32(float c[4], const unsigned a[4],
                                         const unsigned b[2]) {
    asm volatile(
        "mma.sync.aligned.m16n8k8.row.col.f32.tf32.tf32.f32 "
        "{%0,%1,%2,%3},{%4,%5,%6,%7},{%8,%9},{%0,%1,%2,%3};"
        : "+f"(c[0]), "+f"(c[1]), "+f"(c[2]), "+f"(c[3])
        : "r"(a[0]), "r"(a[1]), "r"(a[2]), "r"(a[3]), "r"(b[0]), "r"(b[1]));
}

// ---------------------------------------------------------------------------
// Kernel 1: QKV GEMM (tf32 tensor cores)
//   C[m, 0:768] = gather(x)[m,:] @ Wqkv^T + b ; scatter into g_q/g_k/g_v
//   BM=128, BN=64, BK=32, 8 warps (4M x 2N), warp tile 32x32
// smem layout: As[kq][m][4] (kq = k>>2) -> conflict-free frag LDS + STS.128
// ---------------------------------------------------------------------------
__global__ __launch_bounds__(256) void qkv_gemm(
    const float* __restrict__ x,
    const float* __restrict__ W,
    const float* __restrict__ bias)
{
    __shared__ unsigned As[8 * 512];   // 8 k-quads x 128 m x 4
    __shared__ unsigned Bs[8 * 256];   // 8 k-quads x 64 n  x 4
    __shared__ int rowoff[128];

    const int tid = threadIdx.x;
    const int m0  = blockIdx.y * 128;
    const int n0  = blockIdx.x * 64;

    if (tid < 128) {
        int m    = m0 + tid;
        int bw   = m / 49;
        int n    = m - bw * 49;
        int b    = bw >> 6;
        int widx = bw & 63;
        int wh   = widx >> 3, ww = widx & 7;
        int r    = n / 7,     c  = n - (n / 7) * 7;
        int h = wh * 7 + r + SHIFT_; if (h >= HW) h -= HW;
        int w = ww * 7 + c + SHIFT_; if (w >= HW) w -= HW;
        rowoff[tid] = ((b * HW + h) * HW + w) << 8;
    }
    __syncthreads();

    const int warp  = tid >> 5, lane = tid & 31;
    const int warpM = warp >> 1, warpN = warp & 1;
    const int gid   = lane >> 2, tig = lane & 3;

    // load assignments
    const int arow  = tid >> 1;        // 0..127
    const int khalf = tid & 1;         // 0,1 -> k offset 0/16
    const int bn    = tid & 63;        // 0..63
    const int bkq   = tid >> 6;        // 0..3 (quads bkq and bkq+4)

    float acc[2][4][4];
    #pragma unroll
    for (int mt = 0; mt < 2; mt++)
        #pragma unroll
        for (int nt = 0; nt < 4; nt++)
            #pragma unroll
            for (int e = 0; e < 4; e++) acc[mt][nt][e] = 0.f;

    float4 ar[4], br[2];
    // prologue load kt=0
    #pragma unroll
    for (int j = 0; j < 4; j++)
        ar[j] = *reinterpret_cast<const float4*>(x + rowoff[arow] + khalf*16 + j*4);
    #pragma unroll
    for (int h2 = 0; h2 < 2; h2++)
        br[h2] = *reinterpret_cast<const float4*>(
            W + (size_t)(n0 + bn) * CDIM + (bkq + h2*4) * 4);

    for (int kt = 0; kt < CDIM; kt += 32) {
        // stage regs -> smem (tf32 rounded)
        #pragma unroll
        for (int j = 0; j < 4; j++) {
            uint4 u = { f2tf32(ar[j].x), f2tf32(ar[j].y),
                        f2tf32(ar[j].z), f2tf32(ar[j].w) };
            *reinterpret_cast<uint4*>(&As[(khalf*4 + j)*512 + arow*4]) = u;
        }
        #pragma unroll
        for (int h2 = 0; h2 < 2; h2++) {
            uint4 u = { f2tf32(br[h2].x), f2tf32(br[h2].y),
                        f2tf32(br[h2].z), f2tf32(br[h2].w) };
            *reinterpret_cast<uint4*>(&Bs[(bkq + h2*4)*256 + bn*4]) = u;
        }
        __syncthreads();

        // prefetch next tile while computing
        if (kt + 32 < CDIM) {
            #pragma unroll
            for (int j = 0; j < 4; j++)
                ar[j] = *reinterpret_cast<const float4*>(
                    x + rowoff[arow] + kt + 32 + khalf*16 + j*4);
            #pragma unroll
            for (int h2 = 0; h2 < 2; h2++)
                br[h2] = *reinterpret_cast<const float4*>(
                    W + (size_t)(n0 + bn) * CDIM + kt + 32 + (bkq + h2*4)*4);
        }

        #pragma unroll
        for (int ks = 0; ks < 4; ks++) {
            const int q0 = ks * 2, q1 = ks * 2 + 1;
            unsigned afr[2][4], bfr[4][2];
            #pragma unroll
            for (int mt = 0; mt < 2; mt++) {
                int mr = warpM*32 + mt*16 + gid;
                afr[mt][0] = As[q0*512 + mr*4       + tig];
                afr[mt][1] = As[q0*512 + (mr+8)*4   + tig];
                afr[mt][2] = As[q1*512 + mr*4       + tig];
                afr[mt][3] = As[q1*512 + (mr+8)*4   + tig];
            }
            #pragma unroll
            for (int nt = 0; nt < 4; nt++) {
                int nc = warpN*32 + nt*8 + gid;
                bfr[nt][0] = Bs[q0*256 + nc*4 + tig];
                bfr[nt][1] = Bs[q1*256 + nc*4 + tig];
            }
            #pragma unroll
            for (int mt = 0; mt < 2; mt++)
                #pragma unroll
                for (int nt = 0; nt < 4; nt++)
                    mma_tf32(acc[mt][nt], afr[mt], bfr[nt]);
        }
        __syncthreads();
    }

    // epilogue: scatter into g_q / g_k / g_v with bias (+ q scaling)
    #pragma unroll
    for (int mt = 0; mt < 2; mt++) {
        #pragma unroll
        for (int half = 0; half < 2; half++) {
            int row = m0 + warpM*32 + mt*16 + gid + half*8;
            int bw  = row / 49;
            int n   = row - bw * 49;
            #pragma unroll
            for (int nt = 0; nt < 4; nt++) {
                int col = n0 + warpN*32 + nt*8 + tig*2;
                float v0 = acc[mt][nt][half*2 + 0] + bias[col];
                float v1 = acc[mt][nt][half*2 + 1] + bias[col+1];
                int which = col >> 8;
                int head  = (col >> 5) & 7;
                int d     = col & 31;
                size_t off = (((size_t)bw * HEADS + head) * NTOK + n) * HD + d;
                float2 o;
                if (which == 0) {
                    o.x = v0 * 0.17677669529663687f;
                    o.y = v1 * 0.17677669529663687f;
                    *reinterpret_cast<float2*>(g_q + off) = o;
                } else if (which == 1) {
                    o.x = v0; o.y = v1;
                    *reinterpret_cast<float2*>(g_k + off) = o;
                } else {
                    o.x = v0; o.y = v1;
                    *reinterpret_cast<float2*>(g_v + off) = o;
                }
            }
        }
    }
}

// ---------------------------------------------------------------------------
// Kernel 2: windowed attention — one block (128 thr, 4 warps) per (bw, head).
// Each warp processes 4 query rows per pass: q cached in regs, k/v smem
// loads amortized 4x, softmax in registers (shfl), no block barrier after load.
// ---------------------------------------------------------------------------
__global__ __launch_bounds__(128) void attn_kernel(const float* __restrict__ rel_table)
{
    const int bw   = blockIdx.x >> 3;
    const int head = blockIdx.x & 7;
    const int tid  = threadIdx.x;
    const int w    = tid >> 5;
    const int l    = tid & 31;

    __shared__ float qs[49][36];
    __shared__ float ks[49][36];
    __shared__ float vs[49][36];
    __shared__ float at[16][52];      // warp-private prob rows (4 per warp)
    __shared__ float tab[169];
    __shared__ int   regid[52];

    const size_t base = ((size_t)bw * HEADS + head) * NTOK * HD;
    const float4* q4 = reinterpret_cast<const float4*>(g_q + base);
    const float4* k4 = reinterpret_cast<const float4*>(g_k + base);
    const float4* v4 = reinterpret_cast<const float4*>(g_v + base);
    for (int i = tid; i < 392; i += 128) {          // 49*32/4
        int row = i >> 3, c4 = (i & 7) * 4;
        *reinterpret_cast<float4*>(&qs[row][c4]) = q4[i];
        *reinterpret_cast<float4*>(&ks[row][c4]) = k4[i];
        *reinterpret_cast<float4*>(&vs[row][c4]) = v4[i];
    }
    for (int i = tid; i < 169; i += 128) tab[i] = rel_table[i * HEADS + head];
    if (tid < 49) {
        int widx = bw & 63;
        int wh = widx >> 3, ww = widx & 7;
        int r = tid / 7, c = tid - (tid / 7) * 7;
        int hs = wh * 7 + r, wsp = ww * 7 + c;
        int hr = (hs  < HW - WS) ? 0 : (hs  < HW - SHIFT_ ? 1 : 2);
        int wr = (wsp < HW - WS) ? 0 : (wsp < HW - SHIFT_ ? 1 : 2);
        regid[tid] = hr * 3 + wr;
    }
    __syncthreads();

    // per-lane key metadata
    const int  ma = l;
    const int  mb = l + 32;
    const bool vb = (mb < 49);
    const int  ra = ma / 7, ca = ma - (ma / 7) * 7;
    const int  rb = vb ? mb / 7 : 0, cb = vb ? mb - (mb / 7) * 7 : 0;
    const int  rga = regid[ma];
    const int  rgb = vb ? regid[mb] : -1;

    for (int quad = w; quad < 13; quad += 4) {
        const int nbase = quad * 4;
        // cache 4 q rows in registers
        float4 qv[4][8];
        #pragma unroll
        for (int i = 0; i < 4; i++) {
            int n = nbase + i;
            if (n < 49) {
                #pragma unroll
                for (int j = 0; j < 8; j++)
                    qv[i][j] = *reinterpret_cast<const float4*>(&qs[n][j*4]);
            } else {
                #pragma unroll
                for (int j = 0; j < 8; j++) qv[i][j] = make_float4(0,0,0,0);
            }
        }

        // scores: 4 rows x (m=l, m=l+32)
        float pa[4] = {0,0,0,0}, pb[4] = {0,0,0,0};
        #pragma unroll
        for (int j = 0; j < 8; j++) {
            float4 kva = *reinterpret_cast<const float4*>(&ks[ma][j*4]);
            #pragma unroll
            for (int i = 0; i < 4; i++) {
                pa[i] = fmaf(qv[i][j].x, kva.x, pa[i]);
                pa[i] = fmaf(qv[i][j].y, kva.y, pa[i]);
                pa[i] = fmaf(qv[i][j].z, kva.z, pa[i]);
                pa[i] = fmaf(qv[i][j].w, kva.w, pa[i]);
            }
            if (vb) {
                float4 kvb = *reinterpret_cast<const float4*>(&ks[mb][j*4]);
                #pragma unroll
                for (int i = 0; i < 4; i++) {
                    pb[i] = fmaf(qv[i][j].x, kvb.x, pb[i]);
                    pb[i] = fmaf(qv[i][j].y, kvb.y, pb[i]);
                    pb[i] = fmaf(qv[i][j].z, kvb.z, pb[i]);
                    pb[i] = fmaf(qv[i][j].w, kvb.w, pb[i]);
                }
            }
        }

        // rel-pos bias + shift mask
        #pragma unroll
        for (int i = 0; i < 4; i++) {
            int n = nbase + i;
            if (n < 49) {
                int r1 = n / 7, c1 = n - (n / 7) * 7;
                int rgn = regid[n];
                pa[i] += tab[(r1 - ra + 6) * 13 + (c1 - ca + 6)];
                if (rgn != rga) pa[i] -= 100.f;
                if (vb) {
                    pb[i] += tab[(r1 - rb + 6) * 13 + (c1 - cb + 6)];
                    if (rgn != rgb) pb[i] -= 100.f;
                }
            }
        }

        // softmax per row (registers + shfl), then spill probs
        const int slot = w * 4;
        #pragma unroll
        for (int i = 0; i < 4; i++) {
            float v1 = pa[i];
            float v2 = vb ? pb[i] : -1e30f;
            float mx = fmaxf(v1, v2);
            #pragma unroll
            for (int off = 16; off; off >>= 1)
                mx = fmaxf(mx, __shfl_xor_sync(0xffffffffu, mx, off));
            float e1 = __expf(v1 - mx);
            float e2 = vb ? __expf(v2 - mx) : 0.f;
            float s = e1 + e2;
            #pragma unroll
            for (int off = 16; off; off >>= 1)
                s += __shfl_xor_sync(0xffffffffu, s, off);
            float inv = 1.f / s;
            at[slot + i][l] = e1 * inv;
            if (l < 17) at[slot + i][l + 32] = e2 * inv;
        }
        __syncwarp();

        // AV: lane = output dim d
        float oacc[4] = {0,0,0,0};
        #pragma unroll
        for (int m4 = 0; m4 < 12; m4++) {
            float4 p0 = *reinterpret_cast<const float4*>(&at[slot+0][m4*4]);
            float4 p1 = *reinterpret_cast<const float4*>(&at[slot+1][m4*4]);
            float4 p2 = *reinterpret_cast<const float4*>(&at[slot+2][m4*4]);
            float4 p3 = *reinterpret_cast<const float4*>(&at[slot+3][m4*4]);
            float vv;
            vv = vs[m4*4+0][l];
            oacc[0] = fmaf(p0.x, vv, oacc[0]); oacc[1] = fmaf(p1.x, vv, oacc[1]);
            oacc[2] = fmaf(p2.x, vv, oacc[2]); oacc[3] = fmaf(p3.x, vv, oacc[3]);
            vv = vs[m4*4+1][l];
            oacc[0] = fmaf(p0.y, vv, oacc[0]); oacc[1] = fmaf(p1.y, vv, oacc[1]);
            oacc[2] = fmaf(p2.y, vv, oacc[2]); oacc[3] = fmaf(p3.y, vv, oacc[3]);
            vv = vs[m4*4+2][l];
            oacc[0] = fmaf(p0.z, vv, oacc[0]); oacc[1] = fmaf(p1.z, vv, oacc[1]);
            oacc[2] = fmaf(p2.z, vv, oacc[2]); oacc[3] = fmaf(p3.z, vv, oacc[3]);
            vv = vs[m4*4+3][l];
            oacc[0] = fmaf(p0.w, vv, oacc[0]); oacc[1] = fmaf(p1.w, vv, oacc[1]);
            oacc[2] = fmaf(p2.w, vv, oacc[2]); oacc[3] = fmaf(p3.w, vv, oacc[3]);
        }
        {   // tail m = 48
            float vv = vs[48][l];
            #pragma unroll
            for (int i = 0; i < 4; i++)
                oacc[i] = fmaf(at[slot + i][48], vv, oacc[i]);
        }

        #pragma unroll
        for (int i = 0; i < 4; i++) {
            int n = nbase + i;
            if (n < 49)
                g_ao[((size_t)bw * NTOK + n) * CDIM + head * HD + l] = oacc[i];
        }
        __syncwarp();
    }
}

// ---------------------------------------------------------------------------
// Kernel 3: proj GEMM (tf32) — epilogue scatters (unpartition + unroll) to out
// ---------------------------------------------------------------------------
__global__ __launch_bounds__(256) void proj_gemm(
    const float* __restrict__ W,
    const float* __restrict__ bias,
    float* __restrict__ out)
{
    __shared__ unsigned As[8 * 512];
    __shared__ unsigned Bs[8 * 256];

    const int tid = threadIdx.x;
    const int m0  = blockIdx.y * 128;
    const int n0  = blockIdx.x * 64;

    const int warp  = tid >> 5, lane = tid & 31;
    const int warpM = warp >> 1, warpN = warp & 1;
    const int gid   = lane >> 2, tig = lane & 3;

    const int arow  = tid >> 1;
    const int khalf = tid & 1;
    const int bn    = tid & 63;
    const int bkq   = tid >> 6;

    float acc[2][4][4];
    #pragma unroll
    for (int mt = 0; mt < 2; mt++)
        #pragma unroll
        for (int nt = 0; nt < 4; nt++)
            #pragma unroll
            for (int e = 0; e < 4; e++) acc[mt][nt][e] = 0.f;

    float4 ar[4], br[2];
    #pragma unroll
    for (int j = 0; j < 4; j++)
        ar[j] = *reinterpret_cast<const float4*>(
            g_ao + (size_t)(m0 + arow) * CDIM + khalf*16 + j*4);
    #pragma unroll
    for (int h2 = 0; h2 < 2; h2++)
        br[h2] = *reinterpret_cast<const float4*>(
            W + (size_t)(n0 + bn) * CDIM + (bkq + h2*4) * 4);

    for (int kt = 0; kt < CDIM; kt += 32) {
        #pragma unroll
        for (int j = 0; j < 4; j++) {
            uint4 u = { f2tf32(ar[j].x), f2tf32(ar[j].y),
                        f2tf32(ar[j].z), f2tf32(ar[j].w) };
            *reinterpret_cast<uint4*>(&As[(khalf*4 + j)*512 + arow*4]) = u;
        }
        #pragma unroll
        for (int h2 = 0; h2 < 2; h2++) {
            uint4 u = { f2tf32(br[h2].x), f2tf32(br[h2].y),
                        f2tf32(br[h2].z), f2tf32(br[h2].w) };
            *reinterpret_cast<uint4*>(&Bs[(bkq + h2*4)*256 + bn*4]) = u;
        }
        __syncthreads();

        if (kt + 32 < CDIM) {
            #pragma unroll
            for (int j = 0; j < 4; j++)
                ar[j] = *reinterpret_cast<const float4*>(
                    g_ao + (size_t)(m0 + arow) * CDIM + kt + 32 + khalf*16 + j*4);
            #pragma unroll
            for (int h2 = 0; h2 < 2; h2++)
                br[h2] = *reinterpret_cast<const float4*>(
                    W + (size_t)(n0 + bn) * CDIM + kt + 32 + (bkq + h2*4)*4);
        }

        #pragma unroll
        for (int ks = 0; ks < 4; ks++) {
            const int q0 = ks * 2, q1 = ks * 2 + 1;
            unsigned afr[2][4], bfr[4][2];
            #pragma unroll
            for (int mt = 0; mt < 2; mt++) {
                int mr = warpM*32 + mt*16 + gid;
                afr[mt][0] = As[q0*512 + mr*4     + tig];
                afr[mt][1] = As[q0*512 + (mr+8)*4 + tig];
                afr[mt][2] = As[q1*512 + mr*4     + tig];
                afr[mt][3] = As[q1*512 + (mr+8)*4 + tig];
            }
            #pragma unroll
            for (int nt = 0; nt < 4; nt++) {
                int nc = warpN*32 + nt*8 + gid;
                bfr[nt][0] = Bs[q0*256 + nc*4 + tig];
                bfr[nt][1] = Bs[q1*256 + nc*4 + tig];
            }
            #pragma unroll
            for (int mt = 0; mt < 2; mt++)
                #pragma unroll
                for (int nt = 0; nt < 4; nt++)
                    mma_tf32(acc[mt][nt], afr[mt], bfr[nt]);
        }
        __syncthreads();
    }

    // epilogue: unpartition + inverse roll scatter
    #pragma unroll
    for (int mt = 0; mt < 2; mt++) {
        #pragma unroll
        for (int half = 0; half < 2; half++) {
            int row  = m0 + warpM*32 + mt*16 + gid + half*8;
            int bw   = row / 49;
            int n    = row - bw * 49;
            int b    = bw >> 6;
            int widx = bw & 63;
            int wh   = widx >> 3, ww = widx & 7;
            int r    = n / 7,     c  = n - (n / 7) * 7;
            int h = wh * 7 + r + SHIFT_; if (h >= HW) h -= HW;
            int wp = ww * 7 + c + SHIFT_; if (wp >= HW) wp -= HW;
            size_t obase = ((size_t)(b * HW + h) * HW + wp) * CDIM;
            #pragma unroll
            for (int nt = 0; nt < 4; nt++) {
                int col = n0 + warpN*32 + nt*8 + tig*2;
                float2 o;
                o.x = acc[mt][nt][half*2 + 0] + bias[col];
                o.y = acc[mt][nt][half*2 + 1] + bias[col+1];
                *reinterpret_cast<float2*>(out + obase + col) = o;
            }
        }
    }
}

// ---------------------------------------------------------------------------
// Launch
// ---------------------------------------------------------------------------
extern "C" void kernel_launch(void* const* d_in, const int* in_sizes, int n_in,
                              void* d_out, int out_size)
{
    const float* x     = (const float*)d_in[0];
    const float* qkvw  = (const float*)d_in[1];
    const float* qkvb  = (const float*)d_in[2];
    const float* projw = (const float*)d_in[3];
    const float* projb = (const float*)d_in[4];
    const float* relt  = (const float*)d_in[5];
    float* out = (float*)d_out;

    dim3 g1(3 * CDIM / 64, M_TOT / 128);   // (12, 1568)
    qkv_gemm<<<g1, 256>>>(x, qkvw, qkvb);

    attn_kernel<<<BW_TOT * HEADS, 128>>>(relt);

    dim3 g3(CDIM / 64, M_TOT / 128);       // (4, 1568)
    proj_gemm<<<g3, 256>>>(projw, projb, out);
}

// round 9
// speedup vs baseline: 1.7371x; 1.0002x over previous
#include <cuda_runtime.h>
#include <cuda_bf16.h>

// Problem constants
#define BATCH   64
#define HW      56
#define CDIM    256
#define WS      7
#define SHIFT_  3
#define HEADS   8
#define HD      32
#define NTOK    49
#define BW_TOT  (BATCH*64)              // 4096 window instances
#define M_TOT   (BW_TOT*NTOK)           // 200704 token rows

// ---------------------------------------------------------------------------
// Scratch (device globals: no runtime allocation allowed)
// ---------------------------------------------------------------------------
__device__ float g_q [(size_t)BW_TOT*HEADS*NTOK*HD];   // [bw, head, n, d]
__device__ float g_k [(size_t)BW_TOT*HEADS*NTOK*HD];
__device__ float g_v [(size_t)BW_TOT*HEADS*NTOK*HD];
__device__ float g_ao[(size_t)M_TOT*CDIM];             // attention output [m, C]

// ---------------------------------------------------------------------------
// tf32 helpers
// ---------------------------------------------------------------------------
__device__ __forceinline__ unsigned f2tf32(float f) {
    unsigned u;
    asm("cvt.rna.tf32.f32 %0, %1;" : "=r"(u) : "f"(f));
    return u;
}

__device__ __forceinline__ void mma_tf32(float c[4], const unsigned a[4],
                                         const unsigned b[2]) {
    asm volatile(
        "mma.sync.aligned.m16n8k8.row.col.f32.tf32.tf32.f32 "
        "{%0,%1,%2,%3},{%4,%5,%6,%7},{%8,%9},{%0,%1,%2,%3};"
        : "+f"(c[0]), "+f"(c[1]), "+f"(c[2]), "+f"(c[3])
        : "r"(a[0]), "r"(a[1]), "r"(a[2]), "r"(a[3]), "r"(b[0]), "r"(b[1]));
}

// ---------------------------------------------------------------------------
// Kernel 1: QKV GEMM (tf32 tensor cores)
//   C[m, 0:768] = gather(x)[m,:] @ Wqkv^T + b ; scatter into g_q/g_k/g_v
//   BM=128, BN=64, BK=32, 8 warps (4M x 2N), warp tile 32x32
// smem layout: As[kq][m][4] (kq = k>>2) -> conflict-free frag LDS + STS.128
// ---------------------------------------------------------------------------
__global__ __launch_bounds__(256) void qkv_gemm(
    const float* __restrict__ x,
    const float* __restrict__ W,
    const float* __restrict__ bias)
{
    __shared__ unsigned As[8 * 512];   // 8 k-quads x 128 m x 4
    __shared__ unsigned Bs[8 * 256];   // 8 k-quads x 64 n  x 4
    __shared__ int rowoff[128];

    const int tid = threadIdx.x;
    const int m0  = blockIdx.y * 128;
    const int n0  = blockIdx.x * 64;

    if (tid < 128) {
        int m    = m0 + tid;
        int bw   = m / 49;
        int n    = m - bw * 49;
        int b    = bw >> 6;
        int widx = bw & 63;
        int wh   = widx >> 3, ww = widx & 7;
        int r    = n / 7,     c  = n - (n / 7) * 7;
        int h = wh * 7 + r + SHIFT_; if (h >= HW) h -= HW;
        int w = ww * 7 + c + SHIFT_; if (w >= HW) w -= HW;
        rowoff[tid] = ((b * HW + h) * HW + w) << 8;
    }
    __syncthreads();

    const int warp  = tid >> 5, lane = tid & 31;
    const int warpM = warp >> 1, warpN = warp & 1;
    const int gid   = lane >> 2, tig = lane & 3;

    // load assignments
    const int arow  = tid >> 1;        // 0..127
    const int khalf = tid & 1;         // 0,1 -> k offset 0/16
    const int bn    = tid & 63;        // 0..63
    const int bkq   = tid >> 6;        // 0..3 (quads bkq and bkq+4)

    float acc[2][4][4];
    #pragma unroll
    for (int mt = 0; mt < 2; mt++)
        #pragma unroll
        for (int nt = 0; nt < 4; nt++)
            #pragma unroll
            for (int e = 0; e < 4; e++) acc[mt][nt][e] = 0.f;

    float4 ar[4], br[2];
    // prologue load kt=0
    #pragma unroll
    for (int j = 0; j < 4; j++)
        ar[j] = *reinterpret_cast<const float4*>(x + rowoff[arow] + khalf*16 + j*4);
    #pragma unroll
    for (int h2 = 0; h2 < 2; h2++)
        br[h2] = *reinterpret_cast<const float4*>(
            W + (size_t)(n0 + bn) * CDIM + (bkq + h2*4) * 4);

    for (int kt = 0; kt < CDIM; kt += 32) {
        // stage regs -> smem (tf32 rounded)
        #pragma unroll
        for (int j = 0; j < 4; j++) {
            uint4 u = { f2tf32(ar[j].x), f2tf32(ar[j].y),
                        f2tf32(ar[j].z), f2tf32(ar[j].w) };
            *reinterpret_cast<uint4*>(&As[(khalf*4 + j)*512 + arow*4]) = u;
        }
        #pragma unroll
        for (int h2 = 0; h2 < 2; h2++) {
            uint4 u = { f2tf32(br[h2].x), f2tf32(br[h2].y),
                        f2tf32(br[h2].z), f2tf32(br[h2].w) };
            *reinterpret_cast<uint4*>(&Bs[(bkq + h2*4)*256 + bn*4]) = u;
        }
        __syncthreads();

        // prefetch next tile while computing
        if (kt + 32 < CDIM) {
            #pragma unroll
            for (int j = 0; j < 4; j++)
                ar[j] = *reinterpret_cast<const float4*>(
                    x + rowoff[arow] + kt + 32 + khalf*16 + j*4);
            #pragma unroll
            for (int h2 = 0; h2 < 2; h2++)
                br[h2] = *reinterpret_cast<const float4*>(
                    W + (size_t)(n0 + bn) * CDIM + kt + 32 + (bkq + h2*4)*4);
        }

        #pragma unroll
        for (int ks = 0; ks < 4; ks++) {
            const int q0 = ks * 2, q1 = ks * 2 + 1;
            unsigned afr[2][4], bfr[4][2];
            #pragma unroll
            for (int mt = 0; mt < 2; mt++) {
                int mr = warpM*32 + mt*16 + gid;
                afr[mt][0] = As[q0*512 + mr*4       + tig];
                afr[mt][1] = As[q0*512 + (mr+8)*4   + tig];
                afr[mt][2] = As[q1*512 + mr*4       + tig];
                afr[mt][3] = As[q1*512 + (mr+8)*4   + tig];
            }
            #pragma unroll
            for (int nt = 0; nt < 4; nt++) {
                int nc = warpN*32 + nt*8 + gid;
                bfr[nt][0] = Bs[q0*256 + nc*4 + tig];
                bfr[nt][1] = Bs[q1*256 + nc*4 + tig];
            }
            #pragma unroll
            for (int mt = 0; mt < 2; mt++)
                #pragma unroll
                for (int nt = 0; nt < 4; nt++)
                    mma_tf32(acc[mt][nt], afr[mt], bfr[nt]);
        }
        __syncthreads();
    }

    // epilogue: scatter into g_q / g_k / g_v with bias (+ q scaling)
    #pragma unroll
    for (int mt = 0; mt < 2; mt++) {
        #pragma unroll
        for (int half = 0; half < 2; half++) {
            int row = m0 + warpM*32 + mt*16 + gid + half*8;
            int bw  = row / 49;
            int n   = row - bw * 49;
            #pragma unroll
            for (int nt = 0; nt < 4; nt++) {
                int col = n0 + warpN*32 + nt*8 + tig*2;
                float v0 = acc[mt][nt][half*2 + 0] + bias[col];
                float v1 = acc[mt][nt][half*2 + 1] + bias[col+1];
                int which = col >> 8;
                int head  = (col >> 5) & 7;
                int d     = col & 31;
                size_t off = (((size_t)bw * HEADS + head) * NTOK + n) * HD + d;
                float2 o;
                if (which == 0) {
                    o.x = v0 * 0.17677669529663687f;
                    o.y = v1 * 0.17677669529663687f;
                    *reinterpret_cast<float2*>(g_q + off) = o;
                } else if (which == 1) {
                    o.x = v0; o.y = v1;
                    *reinterpret_cast<float2*>(g_k + off) = o;
                } else {
                    o.x = v0; o.y = v1;
                    *reinterpret_cast<float2*>(g_v + off) = o;
                }
            }
        }
    }
}

// ---------------------------------------------------------------------------
// Kernel 2: windowed attention — one block (128 thr, 4 warps) per (bw, head).
// Each warp processes 4 query rows per pass: q cached in regs, k/v smem
// loads amortized 4x, softmax in registers (shfl), no block barrier after load.
// ---------------------------------------------------------------------------
__global__ __launch_bounds__(128) void attn_kernel(const float* __restrict__ rel_table)
{
    const int bw   = blockIdx.x >> 3;
    const int head = blockIdx.x & 7;
    const int tid  = threadIdx.x;
    const int w    = tid >> 5;
    const int l    = tid & 31;

    __shared__ float qs[49][36];
    __shared__ float ks[49][36];
    __shared__ float vs[49][36];
    __shared__ float at[16][52];      // warp-private prob rows (4 per warp)
    __shared__ float tab[169];
    __shared__ int   regid[52];

    const size_t base = ((size_t)bw * HEADS + head) * NTOK * HD;
    const float4* q4 = reinterpret_cast<const float4*>(g_q + base);
    const float4* k4 = reinterpret_cast<const float4*>(g_k + base);
    const float4* v4 = reinterpret_cast<const float4*>(g_v + base);
    for (int i = tid; i < 392; i += 128) {          // 49*32/4
        int row = i >> 3, c4 = (i & 7) * 4;
        *reinterpret_cast<float4*>(&qs[row][c4]) = q4[i];
        *reinterpret_cast<float4*>(&ks[row][c4]) = k4[i];
        *reinterpret_cast<float4*>(&vs[row][c4]) = v4[i];
    }
    for (int i = tid; i < 169; i += 128) tab[i] = rel_table[i * HEADS + head];
    if (tid < 49) {
        int widx = bw & 63;
        int wh = widx >> 3, ww = widx & 7;
        int r = tid / 7, c = tid - (tid / 7) * 7;
        int hs = wh * 7 + r, wsp = ww * 7 + c;
        int hr = (hs  < HW - WS) ? 0 : (hs  < HW - SHIFT_ ? 1 : 2);
        int wr = (wsp < HW - WS) ? 0 : (wsp < HW - SHIFT_ ? 1 : 2);
        regid[tid] = hr * 3 + wr;
    }
    __syncthreads();

    // per-lane key metadata
    const int  ma = l;
    const int  mb = l + 32;
    const bool vb = (mb < 49);
    const int  ra = ma / 7, ca = ma - (ma / 7) * 7;
    const int  rb = vb ? mb / 7 : 0, cb = vb ? mb - (mb / 7) * 7 : 0;
    const int  rga = regid[ma];
    const int  rgb = vb ? regid[mb] : -1;

    for (int quad = w; quad < 13; quad += 4) {
        const int nbase = quad * 4;
        // cache 4 q rows in registers
        float4 qv[4][8];
        #pragma unroll
        for (int i = 0; i < 4; i++) {
            int n = nbase + i;
            if (n < 49) {
                #pragma unroll
                for (int j = 0; j < 8; j++)
                    qv[i][j] = *reinterpret_cast<const float4*>(&qs[n][j*4]);
            } else {
                #pragma unroll
                for (int j = 0; j < 8; j++) qv[i][j] = make_float4(0,0,0,0);
            }
        }

        // scores: 4 rows x (m=l, m=l+32)
        float pa[4] = {0,0,0,0}, pb[4] = {0,0,0,0};
        #pragma unroll
        for (int j = 0; j < 8; j++) {
            float4 kva = *reinterpret_cast<const float4*>(&ks[ma][j*4]);
            #pragma unroll
            for (int i = 0; i < 4; i++) {
                pa[i] = fmaf(qv[i][j].x, kva.x, pa[i]);
                pa[i] = fmaf(qv[i][j].y, kva.y, pa[i]);
                pa[i] = fmaf(qv[i][j].z, kva.z, pa[i]);
                pa[i] = fmaf(qv[i][j].w, kva.w, pa[i]);
            }
            if (vb) {
                float4 kvb = *reinterpret_cast<const float4*>(&ks[mb][j*4]);
                #pragma unroll
                for (int i = 0; i < 4; i++) {
                    pb[i] = fmaf(qv[i][j].x, kvb.x, pb[i]);
                    pb[i] = fmaf(qv[i][j].y, kvb.y, pb[i]);
                    pb[i] = fmaf(qv[i][j].z, kvb.z, pb[i]);
                    pb[i] = fmaf(qv[i][j].w, kvb.w, pb[i]);
                }
            }
        }

        // rel-pos bias + shift mask
        #pragma unroll
        for (int i = 0; i < 4; i++) {
            int n = nbase + i;
            if (n < 49) {
                int r1 = n / 7, c1 = n - (n / 7) * 7;
                int rgn = regid[n];
                pa[i] += tab[(r1 - ra + 6) * 13 + (c1 - ca + 6)];
                if (rgn != rga) pa[i] -= 100.f;
                if (vb) {
                    pb[i] += tab[(r1 - rb + 6) * 13 + (c1 - cb + 6)];
                    if (rgn != rgb) pb[i] -= 100.f;
                }
            }
        }

        // softmax per row (registers + shfl), then spill probs
        const int slot = w * 4;
        #pragma unroll
        for (int i = 0; i < 4; i++) {
            float v1 = pa[i];
            float v2 = vb ? pb[i] : -1e30f;
            float mx = fmaxf(v1, v2);
            #pragma unroll
            for (int off = 16; off; off >>= 1)
                mx = fmaxf(mx, __shfl_xor_sync(0xffffffffu, mx, off));
            float e1 = __expf(v1 - mx);
            float e2 = vb ? __expf(v2 - mx) : 0.f;
            float s = e1 + e2;
            #pragma unroll
            for (int off = 16; off; off >>= 1)
                s += __shfl_xor_sync(0xffffffffu, s, off);
            float inv = 1.f / s;
            at[slot + i][l] = e1 * inv;
            if (l < 17) at[slot + i][l + 32] = e2 * inv;
        }
        __syncwarp();

        // AV: lane = output dim d
        float oacc[4] = {0,0,0,0};
        #pragma unroll
        for (int m4 = 0; m4 < 12; m4++) {
            float4 p0 = *reinterpret_cast<const float4*>(&at[slot+0][m4*4]);
            float4 p1 = *reinterpret_cast<const float4*>(&at[slot+1][m4*4]);
            float4 p2 = *reinterpret_cast<const float4*>(&at[slot+2][m4*4]);
            float4 p3 = *reinterpret_cast<const float4*>(&at[slot+3][m4*4]);
            float vv;
            vv = vs[m4*4+0][l];
            oacc[0] = fmaf(p0.x, vv, oacc[0]); oacc[1] = fmaf(p1.x, vv, oacc[1]);
            oacc[2] = fmaf(p2.x, vv, oacc[2]); oacc[3] = fmaf(p3.x, vv, oacc[3]);
            vv = vs[m4*4+1][l];
            oacc[0] = fmaf(p0.y, vv, oacc[0]); oacc[1] = fmaf(p1.y, vv, oacc[1]);
            oacc[2] = fmaf(p2.y, vv, oacc[2]); oacc[3] = fmaf(p3.y, vv, oacc[3]);
            vv = vs[m4*4+2][l];
            oacc[0] = fmaf(p0.z, vv, oacc[0]); oacc[1] = fmaf(p1.z, vv, oacc[1]);
            oacc[2] = fmaf(p2.z, vv, oacc[2]); oacc[3] = fmaf(p3.z, vv, oacc[3]);
            vv = vs[m4*4+3][l];
            oacc[0] = fmaf(p0.w, vv, oacc[0]); oacc[1] = fmaf(p1.w, vv, oacc[1]);
            oacc[2] = fmaf(p2.w, vv, oacc[2]); oacc[3] = fmaf(p3.w, vv, oacc[3]);
        }
        {   // tail m = 48
            float vv = vs[48][l];
            #pragma unroll
            for (int i = 0; i < 4; i++)
                oacc[i] = fmaf(at[slot + i][48], vv, oacc[i]);
        }

        #pragma unroll
        for (int i = 0; i < 4; i++) {
            int n = nbase + i;
            if (n < 49)
                g_ao[((size_t)bw * NTOK + n) * CDIM + head * HD + l] = oacc[i];
        }
        __syncwarp();
    }
}

// ---------------------------------------------------------------------------
// Kernel 3: proj GEMM (tf32) — epilogue scatters (unpartition + unroll) to out
// ---------------------------------------------------------------------------
__global__ __launch_bounds__(256) void proj_gemm(
    const float* __restrict__ W,
    const float* __restrict__ bias,
    float* __restrict__ out)
{
    __shared__ unsigned As[8 * 512];
    __shared__ unsigned Bs[8 * 256];

    const int tid = threadIdx.x;
    const int m0  = blockIdx.y * 128;
    const int n0  = blockIdx.x * 64;

    const int warp  = tid >> 5, lane = tid & 31;
    const int warpM = warp >> 1, warpN = warp & 1;
    const int gid   = lane >> 2, tig = lane & 3;

    const int arow  = tid >> 1;
    const int khalf = tid & 1;
    const int bn    = tid & 63;
    const int bkq   = tid >> 6;

    float acc[2][4][4];
    #pragma unroll
    for (int mt = 0; mt < 2; mt++)
        #pragma unroll
        for (int nt = 0; nt < 4; nt++)
            #pragma unroll
            for (int e = 0; e < 4; e++) acc[mt][nt][e] = 0.f;

    float4 ar[4], br[2];
    #pragma unroll
    for (int j = 0; j < 4; j++)
        ar[j] = *reinterpret_cast<const float4*>(
            g_ao + (size_t)(m0 + arow) * CDIM + khalf*16 + j*4);
    #pragma unroll
    for (int h2 = 0; h2 < 2; h2++)
        br[h2] = *reinterpret_cast<const float4*>(
            W + (size_t)(n0 + bn) * CDIM + (bkq + h2*4) * 4);

    for (int kt = 0; kt < CDIM; kt += 32) {
        #pragma unroll
        for (int j = 0; j < 4; j++) {
            uint4 u = { f2tf32(ar[j].x), f2tf32(ar[j].y),
                        f2tf32(ar[j].z), f2tf32(ar[j].w) };
            *reinterpret_cast<uint4*>(&As[(khalf*4 + j)*512 + arow*4]) = u;
        }
        #pragma unroll
        for (int h2 = 0; h2 < 2; h2++) {
            uint4 u = { f2tf32(br[h2].x), f2tf32(br[h2].y),
                        f2tf32(br[h2].z), f2tf32(br[h2].w) };
            *reinterpret_cast<uint4*>(&Bs[(bkq + h2*4)*256 + bn*4]) = u;
        }
        __syncthreads();

        if (kt + 32 < CDIM) {
            #pragma unroll
            for (int j = 0; j < 4; j++)
                ar[j] = *reinterpret_cast<const float4*>(
                    g_ao + (size_t)(m0 + arow) * CDIM + kt + 32 + khalf*16 + j*4);
            #pragma unroll
            for (int h2 = 0; h2 < 2; h2++)
                br[h2] = *reinterpret_cast<const float4*>(
                    W + (size_t)(n0 + bn) * CDIM + kt + 32 + (bkq + h2*4)*4);
        }

        #pragma unroll
        for (int ks = 0; ks < 4; ks++) {
            const int q0 = ks * 2, q1 = ks * 2 + 1;
            unsigned afr[2][4], bfr[4][2];
            #pragma unroll
            for (int mt = 0; mt < 2; mt++) {
                int mr = warpM*32 + mt*16 + gid;
                afr[mt][0] = As[q0*512 + mr*4     + tig];
                afr[mt][1] = As[q0*512 + (mr+8)*4 + tig];
                afr[mt][2] = As[q1*512 + mr*4     + tig];
                afr[mt][3] = As[q1*512 + (mr+8)*4 + tig];
            }
            #pragma unroll
            for (int nt = 0; nt < 4; nt++) {
                int nc = warpN*32 + nt*8 + gid;
                bfr[nt][0] = Bs[q0*256 + nc*4 + tig];
                bfr[nt][1] = Bs[q1*256 + nc*4 + tig];
            }
            #pragma unroll
            for (int mt = 0; mt < 2; mt++)
                #pragma unroll
                for (int nt = 0; nt < 4; nt++)
                    mma_tf32(acc[mt][nt], afr[mt], bfr[nt]);
        }
        __syncthreads();
    }

    // epilogue: unpartition + inverse roll scatter
    #pragma unroll
    for (int mt = 0; mt < 2; mt++) {
        #pragma unroll
        for (int half = 0; half < 2; half++) {
            int row  = m0 + warpM*32 + mt*16 + gid + half*8;
            int bw   = row / 49;
            int n    = row - bw * 49;
            int b    = bw >> 6;
            int widx = bw & 63;
            int wh   = widx >> 3, ww = widx & 7;
            int r    = n / 7,     c  = n - (n / 7) * 7;
            int h = wh * 7 + r + SHIFT_; if (h >= HW) h -= HW;
            int wp = ww * 7 + c + SHIFT_; if (wp >= HW) wp -= HW;
            size_t obase = ((size_t)(b * HW + h) * HW + wp) * CDIM;
            #pragma unroll
            for (int nt = 0; nt < 4; nt++) {
                int col = n0 + warpN*32 + nt*8 + tig*2;
                float2 o;
                o.x = acc[mt][nt][half*2 + 0] + bias[col];
                o.y = acc[mt][nt][half*2 + 1] + bias[col+1];
                *reinterpret_cast<float2*>(out + obase + col) = o;
            }
        }
    }
}

// ---------------------------------------------------------------------------
// Launch
// ---------------------------------------------------------------------------
extern "C" void kernel_launch(void* const* d_in, const int* in_sizes, int n_in,
                              void* d_out, int out_size)
{
    const float* x     = (const float*)d_in[0];
    const float* qkvw  = (const float*)d_in[1];
    const float* qkvb  = (const float*)d_in[2];
    const float* projw = (const float*)d_in[3];
    const float* projb = (const float*)d_in[4];
    const float* relt  = (const float*)d_in[5];
    float* out = (float*)d_out;

    dim3 g1(3 * CDIM / 64, M_TOT / 128);   // (12, 1568)
    qkv_gemm<<<g1, 256>>>(x, qkvw, qkvb);

    attn_kernel<<<BW_TOT * HEADS, 128>>>(relt);

    dim3 g3(CDIM / 64, M_TOT / 128);       // (4, 1568)
    proj_gemm<<<g3, 256>>>(projw, projb, out);
}

// round 10
// speedup vs baseline: 1.7380x; 1.0006x over previous
#include <cuda_runtime.h>
#include <cuda_bf16.h>

// Problem constants
#define BATCH   64
#define HW      56
#define CDIM    256
#define WS      7
#define SHIFT_  3
#define HEADS   8
#define HD      32
#define NTOK    49
#define BW_TOT  (BATCH*64)              // 4096 window instances
#define M_TOT   (BW_TOT*NTOK)           // 200704 token rows

// ---------------------------------------------------------------------------
// Scratch (device globals: no runtime allocation allowed)
// ---------------------------------------------------------------------------
__device__ float g_q [(size_t)BW_TOT*HEADS*NTOK*HD];   // [bw, head, n, d]
__device__ float g_k [(size_t)BW_TOT*HEADS*NTOK*HD];
__device__ float g_v [(size_t)BW_TOT*HEADS*NTOK*HD];
__device__ float g_ao[(size_t)M_TOT*CDIM];             // attention output [m, C]

// ---------------------------------------------------------------------------
// tf32 helpers
// ---------------------------------------------------------------------------
__device__ __forceinline__ unsigned f2tf32(float f) {
    unsigned u;
    asm("cvt.rna.tf32.f32 %0, %1;" : "=r"(u) : "f"(f));
    return u;
}

__device__ __forceinline__ void mma_tf32(float c[4], const unsigned a[4],
                                         const unsigned b[2]) {
    asm volatile(
        "mma.sync.aligned.m16n8k8.row.col.f32.tf32.tf32.f32 "
        "{%0,%1,%2,%3},{%4,%5,%6,%7},{%8,%9},{%0,%1,%2,%3};"
        : "+f"(c[0]), "+f"(c[1]), "+f"(c[2]), "+f"(c[3])
        : "r"(a[0]), "r"(a[1]), "r"(a[2]), "r"(a[3]), "r"(b[0]), "r"(b[1]));
}

// ---------------------------------------------------------------------------
// Kernel 1: QKV GEMM (tf32 tensor cores)
//   C[m, 0:768] = gather(x)[m,:] @ Wqkv^T + b ; scatter into g_q/g_k/g_v
//   BM=128, BN=64, BK=32, 8 warps (4M x 2N), warp tile 32x32
// smem layout: As[kq][m][4] (kq = k>>2) -> conflict-free frag LDS + STS.128
// ---------------------------------------------------------------------------
__global__ __launch_bounds__(256) void qkv_gemm(
    const float* __restrict__ x,
    const float* __restrict__ W,
    const float* __restrict__ bias)
{
    __shared__ unsigned As[8 * 512];   // 8 k-quads x 128 m x 4
    __shared__ unsigned Bs[8 * 256];   // 8 k-quads x 64 n  x 4
    __shared__ int rowoff[128];

    const int tid = threadIdx.x;
    const int m0  = blockIdx.y * 128;
    const int n0  = blockIdx.x * 64;

    if (tid < 128) {
        int m    = m0 + tid;
        int bw   = m / 49;
        int n    = m - bw * 49;
        int b    = bw >> 6;
        int widx = bw & 63;
        int wh   = widx >> 3, ww = widx & 7;
        int r    = n / 7,     c  = n - (n / 7) * 7;
        int h = wh * 7 + r + SHIFT_; if (h >= HW) h -= HW;
        int w = ww * 7 + c + SHIFT_; if (w >= HW) w -= HW;
        rowoff[tid] = ((b * HW + h) * HW + w) << 8;
    }
    __syncthreads();

    const int warp  = tid >> 5, lane = tid & 31;
    const int warpM = warp >> 1, warpN = warp & 1;
    const int gid   = lane >> 2, tig = lane & 3;

    // load assignments
    const int arow  = tid >> 1;        // 0..127
    const int khalf = tid & 1;         // 0,1 -> k offset 0/16
    const int bn    = tid & 63;        // 0..63
    const int bkq   = tid >> 6;        // 0..3 (quads bkq and bkq+4)

    float acc[2][4][4];
    #pragma unroll
    for (int mt = 0; mt < 2; mt++)
        #pragma unroll
        for (int nt = 0; nt < 4; nt++)
            #pragma unroll
            for (int e = 0; e < 4; e++) acc[mt][nt][e] = 0.f;

    float4 ar[4], br[2];
    // prologue load kt=0
    #pragma unroll
    for (int j = 0; j < 4; j++)
        ar[j] = *reinterpret_cast<const float4*>(x + rowoff[arow] + khalf*16 + j*4);
    #pragma unroll
    for (int h2 = 0; h2 < 2; h2++)
        br[h2] = *reinterpret_cast<const float4*>(
            W + (size_t)(n0 + bn) * CDIM + (bkq + h2*4) * 4);

    for (int kt = 0; kt < CDIM; kt += 32) {
        // stage regs -> smem (tf32 rounded)
        #pragma unroll
        for (int j = 0; j < 4; j++) {
            uint4 u = { f2tf32(ar[j].x), f2tf32(ar[j].y),
                        f2tf32(ar[j].z), f2tf32(ar[j].w) };
            *reinterpret_cast<uint4*>(&As[(khalf*4 + j)*512 + arow*4]) = u;
        }
        #pragma unroll
        for (int h2 = 0; h2 < 2; h2++) {
            uint4 u = { f2tf32(br[h2].x), f2tf32(br[h2].y),
                        f2tf32(br[h2].z), f2tf32(br[h2].w) };
            *reinterpret_cast<uint4*>(&Bs[(bkq + h2*4)*256 + bn*4]) = u;
        }
        __syncthreads();

        // prefetch next tile while computing
        if (kt + 32 < CDIM) {
            #pragma unroll
            for (int j = 0; j < 4; j++)
                ar[j] = *reinterpret_cast<const float4*>(
                    x + rowoff[arow] + kt + 32 + khalf*16 + j*4);
            #pragma unroll
            for (int h2 = 0; h2 < 2; h2++)
                br[h2] = *reinterpret_cast<const float4*>(
                    W + (size_t)(n0 + bn) * CDIM + kt + 32 + (bkq + h2*4)*4);
        }

        #pragma unroll
        for (int ks = 0; ks < 4; ks++) {
            const int q0 = ks * 2, q1 = ks * 2 + 1;
            unsigned afr[2][4], bfr[4][2];
            #pragma unroll
            for (int mt = 0; mt < 2; mt++) {
                int mr = warpM*32 + mt*16 + gid;
                afr[mt][0] = As[q0*512 + mr*4       + tig];
                afr[mt][1] = As[q0*512 + (mr+8)*4   + tig];
                afr[mt][2] = As[q1*512 + mr*4       + tig];
                afr[mt][3] = As[q1*512 + (mr+8)*4   + tig];
            }
            #pragma unroll
            for (int nt = 0; nt < 4; nt++) {
                int nc = warpN*32 + nt*8 + gid;
                bfr[nt][0] = Bs[q0*256 + nc*4 + tig];
                bfr[nt][1] = Bs[q1*256 + nc*4 + tig];
            }
            #pragma unroll
            for (int mt = 0; mt < 2; mt++)
                #pragma unroll
                for (int nt = 0; nt < 4; nt++)
                    mma_tf32(acc[mt][nt], afr[mt], bfr[nt]);
        }
        __syncthreads();
    }

    // epilogue: scatter into g_q / g_k / g_v with bias (+ q scaling)
    #pragma unroll
    for (int mt = 0; mt < 2; mt++) {
        #pragma unroll
        for (int half = 0; half < 2; half++) {
            int row = m0 + warpM*32 + mt*16 + gid + half*8;
            int bw  = row / 49;
            int n   = row - bw * 49;
            #pragma unroll
            for (int nt = 0; nt < 4; nt++) {
                int col = n0 + warpN*32 + nt*8 + tig*2;
                float v0 = acc[mt][nt][half*2 + 0] + bias[col];
                float v1 = acc[mt][nt][half*2 + 1] + bias[col+1];
                int which = col >> 8;
                int head  = (col >> 5) & 7;
                int d     = col & 31;
                size_t off = (((size_t)bw * HEADS + head) * NTOK + n) * HD + d;
                float2 o;
                if (which == 0) {
                    o.x = v0 * 0.17677669529663687f;
                    o.y = v1 * 0.17677669529663687f;
                    *reinterpret_cast<float2*>(g_q + off) = o;
                } else if (which == 1) {
                    o.x = v0; o.y = v1;
                    *reinterpret_cast<float2*>(g_k + off) = o;
                } else {
                    o.x = v0; o.y = v1;
                    *reinterpret_cast<float2*>(g_v + off) = o;
                }
            }
        }
    }
}

// ---------------------------------------------------------------------------
// Kernel 2: windowed attention — one block (128 thr, 4 warps) per (bw, head).
// Each warp processes 4 query rows per pass: q cached in regs, k/v smem
// loads amortized 4x, softmax in registers (shfl), no block barrier after load.
// ---------------------------------------------------------------------------
__global__ __launch_bounds__(128) void attn_kernel(const float* __restrict__ rel_table)
{
    const int bw   = blockIdx.x >> 3;
    const int head = blockIdx.x & 7;
    const int tid  = threadIdx.x;
    const int w    = tid >> 5;
    const int l    = tid & 31;

    __shared__ float qs[49][36];
    __shared__ float ks[49][36];
    __shared__ float vs[49][36];
    __shared__ float at[16][52];      // warp-private prob rows (4 per warp)
    __shared__ float tab[169];
    __shared__ int   regid[52];

    const size_t base = ((size_t)bw * HEADS + head) * NTOK * HD;
    const float4* q4 = reinterpret_cast<const float4*>(g_q + base);
    const float4* k4 = reinterpret_cast<const float4*>(g_k + base);
    const float4* v4 = reinterpret_cast<const float4*>(g_v + base);
    for (int i = tid; i < 392; i += 128) {          // 49*32/4
        int row = i >> 3, c4 = (i & 7) * 4;
        *reinterpret_cast<float4*>(&qs[row][c4]) = q4[i];
        *reinterpret_cast<float4*>(&ks[row][c4]) = k4[i];
        *reinterpret_cast<float4*>(&vs[row][c4]) = v4[i];
    }
    for (int i = tid; i < 169; i += 128) tab[i] = rel_table[i * HEADS + head];
    if (tid < 49) {
        int widx = bw & 63;
        int wh = widx >> 3, ww = widx & 7;
        int r = tid / 7, c = tid - (tid / 7) * 7;
        int hs = wh * 7 + r, wsp = ww * 7 + c;
        int hr = (hs  < HW - WS) ? 0 : (hs  < HW - SHIFT_ ? 1 : 2);
        int wr = (wsp < HW - WS) ? 0 : (wsp < HW - SHIFT_ ? 1 : 2);
        regid[tid] = hr * 3 + wr;
    }
    __syncthreads();

    // per-lane key metadata
    const int  ma = l;
    const int  mb = l + 32;
    const bool vb = (mb < 49);
    const int  ra = ma / 7, ca = ma - (ma / 7) * 7;
    const int  rb = vb ? mb / 7 : 0, cb = vb ? mb - (mb / 7) * 7 : 0;
    const int  rga = regid[ma];
    const int  rgb = vb ? regid[mb] : -1;

    for (int quad = w; quad < 13; quad += 4) {
        const int nbase = quad * 4;
        // cache 4 q rows in registers
        float4 qv[4][8];
        #pragma unroll
        for (int i = 0; i < 4; i++) {
            int n = nbase + i;
            if (n < 49) {
                #pragma unroll
                for (int j = 0; j < 8; j++)
                    qv[i][j] = *reinterpret_cast<const float4*>(&qs[n][j*4]);
            } else {
                #pragma unroll
                for (int j = 0; j < 8; j++) qv[i][j] = make_float4(0,0,0,0);
            }
        }

        // scores: 4 rows x (m=l, m=l+32)
        float pa[4] = {0,0,0,0}, pb[4] = {0,0,0,0};
        #pragma unroll
        for (int j = 0; j < 8; j++) {
            float4 kva = *reinterpret_cast<const float4*>(&ks[ma][j*4]);
            #pragma unroll
            for (int i = 0; i < 4; i++) {
                pa[i] = fmaf(qv[i][j].x, kva.x, pa[i]);
                pa[i] = fmaf(qv[i][j].y, kva.y, pa[i]);
                pa[i] = fmaf(qv[i][j].z, kva.z, pa[i]);
                pa[i] = fmaf(qv[i][j].w, kva.w, pa[i]);
            }
            if (vb) {
                float4 kvb = *reinterpret_cast<const float4*>(&ks[mb][j*4]);
                #pragma unroll
                for (int i = 0; i < 4; i++) {
                    pb[i] = fmaf(qv[i][j].x, kvb.x, pb[i]);
                    pb[i] = fmaf(qv[i][j].y, kvb.y, pb[i]);
                    pb[i] = fmaf(qv[i][j].z, kvb.z, pb[i]);
                    pb[i] = fmaf(qv[i][j].w, kvb.w, pb[i]);
                }
            }
        }

        // rel-pos bias + shift mask
        #pragma unroll
        for (int i = 0; i < 4; i++) {
            int n = nbase + i;
            if (n < 49) {
                int r1 = n / 7, c1 = n - (n / 7) * 7;
                int rgn = regid[n];
                pa[i] += tab[(r1 - ra + 6) * 13 + (c1 - ca + 6)];
                if (rgn != rga) pa[i] -= 100.f;
                if (vb) {
                    pb[i] += tab[(r1 - rb + 6) * 13 + (c1 - cb + 6)];
                    if (rgn != rgb) pb[i] -= 100.f;
                }
            }
        }

        // softmax per row (registers + shfl), then spill probs
        const int slot = w * 4;
        #pragma unroll
        for (int i = 0; i < 4; i++) {
            float v1 = pa[i];
            float v2 = vb ? pb[i] : -1e30f;
            float mx = fmaxf(v1, v2);
            #pragma unroll
            for (int off = 16; off; off >>= 1)
                mx = fmaxf(mx, __shfl_xor_sync(0xffffffffu, mx, off));
            float e1 = __expf(v1 - mx);
            float e2 = vb ? __expf(v2 - mx) : 0.f;
            float s = e1 + e2;
            #pragma unroll
            for (int off = 16; off; off >>= 1)
                s += __shfl_xor_sync(0xffffffffu, s, off);
            float inv = 1.f / s;
            at[slot + i][l] = e1 * inv;
            if (l < 17) at[slot + i][l + 32] = e2 * inv;
        }
        __syncwarp();

        // AV: lane = output dim d
        float oacc[4] = {0,0,0,0};
        #pragma unroll
        for (int m4 = 0; m4 < 12; m4++) {
            float4 p0 = *reinterpret_cast<const float4*>(&at[slot+0][m4*4]);
            float4 p1 = *reinterpret_cast<const float4*>(&at[slot+1][m4*4]);
            float4 p2 = *reinterpret_cast<const float4*>(&at[slot+2][m4*4]);
            float4 p3 = *reinterpret_cast<const float4*>(&at[slot+3][m4*4]);
            float vv;
            vv = vs[m4*4+0][l];
            oacc[0] = fmaf(p0.x, vv, oacc[0]); oacc[1] = fmaf(p1.x, vv, oacc[1]);
            oacc[2] = fmaf(p2.x, vv, oacc[2]); oacc[3] = fmaf(p3.x, vv, oacc[3]);
            vv = vs[m4*4+1][l];
            oacc[0] = fmaf(p0.y, vv, oacc[0]); oacc[1] = fmaf(p1.y, vv, oacc[1]);
            oacc[2] = fmaf(p2.y, vv, oacc[2]); oacc[3] = fmaf(p3.y, vv, oacc[3]);
            vv = vs[m4*4+2][l];
            oacc[0] = fmaf(p0.z, vv, oacc[0]); oacc[1] = fmaf(p1.z, vv, oacc[1]);
            oacc[2] = fmaf(p2.z, vv, oacc[2]); oacc[3] = fmaf(p3.z, vv, oacc[3]);
            vv = vs[m4*4+3][l];
            oacc[0] = fmaf(p0.w, vv, oacc[0]); oacc[1] = fmaf(p1.w, vv, oacc[1]);
            oacc[2] = fmaf(p2.w, vv, oacc[2]); oacc[3] = fmaf(p3.w, vv, oacc[3]);
        }
        {   // tail m = 48
            float vv = vs[48][l];
            #pragma unroll
            for (int i = 0; i < 4; i++)
                oacc[i] = fmaf(at[slot + i][48], vv, oacc[i]);
        }

        #pragma unroll
        for (int i = 0; i < 4; i++) {
            int n = nbase + i;
            if (n < 49)
                g_ao[((size_t)bw * NTOK + n) * CDIM + head * HD + l] = oacc[i];
        }
        __syncwarp();
    }
}

// ---------------------------------------------------------------------------
// Kernel 3: proj GEMM (tf32) — epilogue scatters (unpartition + unroll) to out
// ---------------------------------------------------------------------------
__global__ __launch_bounds__(256) void proj_gemm(
    const float* __restrict__ W,
    const float* __restrict__ bias,
    float* __restrict__ out)
{
    __shared__ unsigned As[8 * 512];
    __shared__ unsigned Bs[8 * 256];

    const int tid = threadIdx.x;
    const int m0  = blockIdx.y * 128;
    const int n0  = blockIdx.x * 64;

    const int warp  = tid >> 5, lane = tid & 31;
    const int warpM = warp >> 1, warpN = warp & 1;
    const int gid   = lane >> 2, tig = lane & 3;

    const int arow  = tid >> 1;
    const int khalf = tid & 1;
    const int bn    = tid & 63;
    const int bkq   = tid >> 6;

    float acc[2][4][4];
    #pragma unroll
    for (int mt = 0; mt < 2; mt++)
        #pragma unroll
        for (int nt = 0; nt < 4; nt++)
            #pragma unroll
            for (int e = 0; e < 4; e++) acc[mt][nt][e] = 0.f;

    float4 ar[4], br[2];
    #pragma unroll
    for (int j = 0; j < 4; j++)
        ar[j] = *reinterpret_cast<const float4*>(
            g_ao + (size_t)(m0 + arow) * CDIM + khalf*16 + j*4);
    #pragma unroll
    for (int h2 = 0; h2 < 2; h2++)
        br[h2] = *reinterpret_cast<const float4*>(
            W + (size_t)(n0 + bn) * CDIM + (bkq + h2*4) * 4);

    for (int kt = 0; kt < CDIM; kt += 32) {
        #pragma unroll
        for (int j = 0; j < 4; j++) {
            uint4 u = { f2tf32(ar[j].x), f2tf32(ar[j].y),
                        f2tf32(ar[j].z), f2tf32(ar[j].w) };
            *reinterpret_cast<uint4*>(&As[(khalf*4 + j)*512 + arow*4]) = u;
        }
        #pragma unroll
        for (int h2 = 0; h2 < 2; h2++) {
            uint4 u = { f2tf32(br[h2].x), f2tf32(br[h2].y),
                        f2tf32(br[h2].z), f2tf32(br[h2].w) };
            *reinterpret_cast<uint4*>(&Bs[(bkq + h2*4)*256 + bn*4]) = u;
        }
        __syncthreads();

        if (kt + 32 < CDIM) {
            #pragma unroll
            for (int j = 0; j < 4; j++)
                ar[j] = *reinterpret_cast<const float4*>(
                    g_ao + (size_t)(m0 + arow) * CDIM + kt + 32 + khalf*16 + j*4);
            #pragma unroll
            for (int h2 = 0; h2 < 2; h2++)
                br[h2] = *reinterpret_cast<const float4*>(
                    W + (size_t)(n0 + bn) * CDIM + kt + 32 + (bkq + h2*4)*4);
        }

        #pragma unroll
        for (int ks = 0; ks < 4; ks++) {
            const int q0 = ks * 2, q1 = ks * 2 + 1;
            unsigned afr[2][4], bfr[4][2];
            #pragma unroll
            for (int mt = 0; mt < 2; mt++) {
                int mr = warpM*32 + mt*16 + gid;
                afr[mt][0] = As[q0*512 + mr*4     + tig];
                afr[mt][1] = As[q0*512 + (mr+8)*4 + tig];
                afr[mt][2] = As[q1*512 + mr*4     + tig];
                afr[mt][3] = As[q1*512 + (mr+8)*4 + tig];
            }
            #pragma unroll
            for (int nt = 0; nt < 4; nt++) {
                int nc = warpN*32 + nt*8 + gid;
                bfr[nt][0] = Bs[q0*256 + nc*4 + tig];
                bfr[nt][1] = Bs[q1*256 + nc*4 + tig];
            }
            #pragma unroll
            for (int mt = 0; mt < 2; mt++)
                #pragma unroll
                for (int nt = 0; nt < 4; nt++)
                    mma_tf32(acc[mt][nt], afr[mt], bfr[nt]);
        }
        __syncthreads();
    }

    // epilogue: unpartition + inverse roll scatter
    #pragma unroll
    for (int mt = 0; mt < 2; mt++) {
        #pragma unroll
        for (int half = 0; half < 2; half++) {
            int row  = m0 + warpM*32 + mt*16 + gid + half*8;
            int bw   = row / 49;
            int n    = row - bw * 49;
            int b    = bw >> 6;
            int widx = bw & 63;
            int wh   = widx >> 3, ww = widx & 7;
            int r    = n / 7,     c  = n - (n / 7) * 7;
            int h = wh * 7 + r + SHIFT_; if (h >= HW) h -= HW;
            int wp = ww * 7 + c + SHIFT_; if (wp >= HW) wp -= HW;
            size_t obase = ((size_t)(b * HW + h) * HW + wp) * CDIM;
            #pragma unroll
            for (int nt = 0; nt < 4; nt++) {
                int col = n0 + warpN*32 + nt*8 + tig*2;
                float2 o;
                o.x = acc[mt][nt][half*2 + 0] + bias[col];
                o.y = acc[mt][nt][half*2 + 1] + bias[col+1];
                *reinterpret_cast<float2*>(out + obase + col) = o;
            }
        }
    }
}

// ---------------------------------------------------------------------------
// Launch
// ---------------------------------------------------------------------------
extern "C" void kernel_launch(void* const* d_in, const int* in_sizes, int n_in,
                              void* d_out, int out_size)
{
    const float* x     = (const float*)d_in[0];
    const float* qkvw  = (const float*)d_in[1];
    const float* qkvb  = (const float*)d_in[2];
    const float* projw = (const float*)d_in[3];
    const float* projb = (const float*)d_in[4];
    const float* relt  = (const float*)d_in[5];
    float* out = (float*)d_out;

    dim3 g1(3 * CDIM / 64, M_TOT / 128);   // (12, 1568)
    qkv_gemm<<<g1, 256>>>(x, qkvw, qkvb);

    attn_kernel<<<BW_TOT * HEADS, 128>>>(relt);

    dim3 g3(CDIM / 64, M_TOT / 128);       // (4, 1568)
    proj_gemm<<<g3, 256>>>(projw, projb, out);
}